// round 7
// baseline (speedup 1.0000x reference)
#include <cuda_runtime.h>
#include <cuda_bf16.h>

// JointBilateral upsample, S=4, K=5. Block = 512 threads covering a full
// 4-row x 512-col output stripe: q = tid&127 (4 cols each), s = tid>>7 (row).
// s is warp-uniform. Tap values are published through shared memory:
//   - first tap (4p+1, 4q+1) = s==1 thread's center .y (3 channels) + x row
//   - second-row tap (4p+5, 4q+1) loaded & published by s==3 warps
// Second-col / corner taps = smem[q+1] (always in-block; q=127 predicated off).
//
// e(tap) = exp(-0.125*||g_tap - g_ctr||^2) * exp(-0.005*((i-2)^2+(j-2)^2))
// out = sum(e * wgt[4-i][4-j] * x_tap) / sum(e)
// MUFU-free: cubic exp(-z) for z in [0,0.094], Newton reciprocal.

#define CH  (512 * 512)
#define E1  0.9950124791926823f   /* exp(-0.005) */
#define E4  0.9801986733067553f   /* exp(-0.020) */

__device__ __forceinline__ float exp_neg_small(float z)
{
    float p = fmaf(-0.16666667f, z, 0.5f);
    p = fmaf(p, z, -1.0f);
    return fmaf(p, z, 1.0f);
}

__device__ __forceinline__ float fast_rcp(float x)
{
    float r = __uint_as_float(0x7EF311C3u - __float_as_uint(x));
    r = r * fmaf(-x, r, 2.0f);
    r = r * fmaf(-x, r, 2.0f);
    return r;
}

__global__ void __launch_bounds__(512, 4) jb_kernel(
    const float* __restrict__ x,
    const float* __restrict__ g,
    const float* __restrict__ wgt,
    float* __restrict__ out)
{
    __shared__ float sm_t0[129], sm_t1[129], sm_t2[129], sm_x[129];
    __shared__ float sm_v0[129], sm_v1[129], sm_v2[129], sm_vx[129];

    int tid = threadIdx.x;
    int q = tid & 127;
    int s = tid >> 7;                 // warp-uniform (warp>>2)
    int blk = blockIdx.x;             // 512 blocks = 4 b * 128 p
    int p = blk & 127;
    int b = blk >> 7;

    const float* gb = g + (size_t)b * 3 * CH;
    const float* xb = x + b * (128 * 128);

    int hrow = (4 * p + s) * 512 + 4 * q;

    float4 c0 = *(const float4*)(gb + hrow);
    float4 c1 = *(const float4*)(gb + CH + hrow);
    float4 c2 = *(const float4*)(gb + 2 * CH + hrow);

    bool row2 = (p < 127);
    bool col2 = (q < 127);

    if (s == 1) {                     // publish first-tap values + x row
        sm_t0[q] = c0.y;
        sm_t1[q] = c1.y;
        sm_t2[q] = c2.y;
        sm_x[q]  = xb[p * 128 + q];
    }
    if (s == 3) {                     // publish second-row tap + x (clamped)
        int vr = row2 ? (4 * p + 5) : (4 * p + 1);
        int ov = vr * 512 + 4 * q + 1;
        sm_v0[q] = gb[ov];
        sm_v1[q] = gb[ov + CH];
        sm_v2[q] = gb[ov + 2 * CH];
        sm_vx[q] = xb[(p + (row2 ? 1 : 0)) * 128 + q];
    }
    if (tid == 0) {                   // dummies for the q=127 (unused) reads
        sm_t0[128] = 0.f; sm_t1[128] = 0.f; sm_t2[128] = 0.f; sm_x[128] = 0.f;
        sm_v0[128] = 0.f; sm_v1[128] = 0.f; sm_v2[128] = 0.f; sm_vx[128] = 0.f;
    }
    __syncthreads();

    float t0 = sm_t0[q], t1 = sm_t1[q], t2 = sm_t2[q];
    float u0 = sm_t0[q + 1], u1 = sm_t1[q + 1], u2 = sm_t2[q + 1];
    float x00 = sm_x[q], x01 = sm_x[q + 1];

    // weights for this output row (warp-uniform addresses)
    float wA0 = wgt[(s + 1) * 5 + 1] * x00;
    float wA1 = wgt[(s + 1) * 5 + 2] * x00;
    float wA2 = wgt[(s + 1) * 5 + 3] * x00;
    float wA3 = wgt[(s + 1) * 5 + 4] * x00;
    float wCol = wgt[(s + 1) * 5] * x01;

    float espS = (s == 1) ? 1.0f : ((s == 3) ? E4 : E1);

    float ctr0[4] = {c0.x, c0.y, c0.z, c0.w};
    float ctr1[4] = {c1.x, c1.y, c1.z, c1.w};
    float ctr2[4] = {c2.x, c2.y, c2.z, c2.w};
    float wAr[4]  = {wA0, wA1, wA2, wA3};
    const float espC[4] = {E1, 1.0f, E1, E4};

    float num[4], den[4];
#pragma unroll
    for (int r = 0; r < 4; r++) {
        float d0 = t0 - ctr0[r];
        float d1 = t1 - ctr1[r];
        float d2 = t2 - ctr2[r];
        float z = 0.125f * fmaf(d0, d0, fmaf(d1, d1, d2 * d2));
        float e = exp_neg_small(z) * (espS * espC[r]);
        den[r] = e;
        num[r] = e * wAr[r];
    }
    {   // second-col tap for r=3
        float h0 = u0 - ctr0[3];
        float h1 = u1 - ctr1[3];
        float h2 = u2 - ctr2[3];
        float z = 0.125f * fmaf(h0, h0, fmaf(h1, h1, h2 * h2));
        float e3 = exp_neg_small(z) * (espS * E4);
        if (col2) { den[3] += e3; num[3] += e3 * wCol; }
    }

    if (s == 3 && row2) {             // warp-uniform second-row taps
        float v0 = sm_v0[q], v1 = sm_v1[q], v2 = sm_v2[q];
        float x10 = sm_vx[q];
#pragma unroll
        for (int r = 0; r < 4; r++) {
            float f0 = v0 - ctr0[r];
            float f1 = v1 - ctr1[r];
            float f2 = v2 - ctr2[r];
            float z = 0.125f * fmaf(f0, f0, fmaf(f1, f1, f2 * f2));
            float e2 = exp_neg_small(z) * (E4 * espC[r]);
            den[r] += e2;
            num[r] += e2 * wgt[r + 1] * x10;
        }
        if (col2) {                   // corner tap
            float k0 = sm_v0[q + 1] - ctr0[3];
            float k1 = sm_v1[q + 1] - ctr1[3];
            float k2 = sm_v2[q + 1] - ctr2[3];
            float zz = 0.125f * fmaf(k0, k0, fmaf(k1, k1, k2 * k2));
            float e4 = exp_neg_small(zz) * (E4 * E4);
            den[3] += e4;
            num[3] += e4 * wgt[0] * sm_vx[q + 1];
        }
    }

    float4 o = make_float4(num[0] * fast_rcp(den[0]),
                           num[1] * fast_rcp(den[1]),
                           num[2] * fast_rcp(den[2]),
                           num[3] * fast_rcp(den[3]));
    *(float4*)(out + (size_t)b * CH + hrow) = o;
}

extern "C" void kernel_launch(void* const* d_in, const int* in_sizes, int n_in,
                              void* d_out, int out_size)
{
    const float* x   = (const float*)d_in[0];
    const float* g   = (const float*)d_in[1];
    const float* wgt = (const float*)d_in[2];
    float* out = (float*)d_out;

    // 512 blocks: 4 batches * 128 p ; 512 threads: 4 s-rows * 128 q
    jb_kernel<<<512, 512>>>(x, g, wgt, out);
}